// round 13
// baseline (speedup 1.0000x reference)
#include <cuda_runtime.h>
#include <cuda_fp16.h>
#include <cstdint>

#define D 128
#define NMAX 100000
#define EMAX 1600000
#define SCH 512
#define GT 128                // gemm M tile
#define AST 136               // padded smem row stride (fp16 elems)

// Scratch (device globals — no runtime allocation allowed)
// xl / xr double-buffered per layer (race-free gemm2 || agg1 overlap).
__device__ __half g_xl_h[2][(size_t)NMAX * D]; // A @ W_l (fp16, gather-only)
__device__ float  g_xr[2][(size_t)NMAX * D];   // A @ W_r
__device__ float  g_h [(size_t)NMAX * D];      // layer-1 output
__device__ __half g_wt[4 * D * D];             // W^T fp16: Wl1,Wr1,Wl2,Wr2 ([n][k] row-major)
__device__ float  g_inv[NMAX];
__device__ int    g_cnt[NMAX];
__device__ int    g_fill[NMAX];
__device__ int    g_rowptr[NMAX + 1];
__device__ int    g_srcs[EMAX];
__device__ int    g_bsum[256];

// ---------------------------------------------------------------------------
__device__ __forceinline__ uint32_t smem_u32(const void* p) {
    uint32_t a;
    asm("{ .reg .u64 t; cvta.to.shared.u64 t, %1; cvt.u32.u64 %0, t; }" : "=r"(a) : "l"(p));
    return a;
}
// fp16 hi/lo split: x = hi + lo with |residual| ~ 6e-8 relative
__device__ __forceinline__ void split_pack_h(const float4 v, uint2& uhi, uint2& ulo) {
    __half2 h01 = __floats2half2_rn(v.x, v.y);
    __half2 h23 = __floats2half2_rn(v.z, v.w);
    float2 f01 = __half22float2(h01), f23 = __half22float2(h23);
    __half2 l01 = __floats2half2_rn(v.x - f01.x, v.y - f01.y);
    __half2 l23 = __floats2half2_rn(v.z - f23.x, v.w - f23.y);
    uhi.x = *(uint32_t*)&h01; uhi.y = *(uint32_t*)&h23;
    ulo.x = *(uint32_t*)&l01; ulo.y = *(uint32_t*)&l23;
}
#define LDSM4(r0, r1, r2, r3, a) \
    asm volatile("ldmatrix.sync.aligned.m8n8.x4.shared.b16 {%0,%1,%2,%3}, [%4];" \
                 : "=r"(r0), "=r"(r1), "=r"(r2), "=r"(r3) : "r"(a))
#define MMA16816(c, a, b) \
    asm volatile("mma.sync.aligned.m16n8k16.row.col.f32.f16.f16.f32 " \
                 "{%0,%1,%2,%3}, {%4,%5,%6,%7}, {%8,%9}, {%0,%1,%2,%3};" \
                 : "+f"((c)[0]), "+f"((c)[1]), "+f"((c)[2]), "+f"((c)[3]) \
                 : "r"((a)[0]), "r"((a)[1]), "r"((a)[2]), "r"((a)[3]), \
                   "r"((b)[0]), "r"((b)[1]))

// ---------------------------------------------------------------------------
// CSR build
// ---------------------------------------------------------------------------
__global__ void zero_cnt_kernel(int N) {
    int i = blockIdx.x * blockDim.x + threadIdx.x;
    if (i < N) g_cnt[i] = 0;
}
__global__ void hist_kernel(const int* __restrict__ ei, int E) {
    int e = blockIdx.x * blockDim.x + threadIdx.x;
    if (e < E) atomicAdd(&g_cnt[ei[E + e]], 1);
}
__global__ __launch_bounds__(SCH) void scan1_kernel(int N) {
    __shared__ int sh[SCH];
    int t = threadIdx.x;
    int gi = blockIdx.x * SCH + t;
    sh[t] = (gi < N) ? g_cnt[gi] : 0;
    __syncthreads();
#pragma unroll
    for (int off = 1; off < SCH; off <<= 1) {
        int y = (t >= off) ? sh[t - off] : 0;
        __syncthreads();
        sh[t] += y;
        __syncthreads();
    }
    if (gi < N) g_rowptr[gi + 1] = sh[t];
    if (t == SCH - 1) g_bsum[blockIdx.x] = sh[t];
}
__global__ __launch_bounds__(256) void scan2_kernel(int nblocks) {
    __shared__ int sh[256];
    int t = threadIdx.x;
    sh[t] = (t < nblocks) ? g_bsum[t] : 0;
    __syncthreads();
#pragma unroll
    for (int off = 1; off < 256; off <<= 1) {
        int y = (t >= off) ? sh[t - off] : 0;
        __syncthreads();
        sh[t] += y;
        __syncthreads();
    }
    if (t < nblocks) g_bsum[t] = (t > 0) ? sh[t - 1] : 0;
}
__global__ void scan3_kernel(int N) {
    int i = blockIdx.x * blockDim.x + threadIdx.x;
    if (i >= N) return;
    int incl = g_rowptr[i + 1] + g_bsum[i / SCH];
    g_rowptr[i + 1] = incl;
    g_inv[i] = 1.0f / fmaxf((float)g_cnt[i], 1.0f);
    g_fill[i] = incl - g_cnt[i];   // cursor starts at rowptr[i]
    if (i == 0) g_rowptr[0] = 0;
}
__global__ void fill_kernel(const int* __restrict__ ei, int E) {
    int e = blockIdx.x * blockDim.x + threadIdx.x;
    if (e >= E) return;
    int d = ei[E + e];
    int pos = atomicAdd(&g_fill[d], 1);
    g_srcs[pos] = ei[e];
}

// ---------------------------------------------------------------------------
// wtrans: W[k][n] fp32 -> W^T[n][k] fp16 (4 matrices, row-major)
// ---------------------------------------------------------------------------
__global__ __launch_bounds__(256) void wtrans_kernel(
    const float* __restrict__ Wl1, const float* __restrict__ Wr1,
    const float* __restrict__ Wl2, const float* __restrict__ Wr2)
{
    int t = blockIdx.x * blockDim.x + threadIdx.x;   // 0 .. 16383
    int mat = t >> 12;
    int rem = t & 4095;
    int n = rem >> 5;
    int cg = (rem & 31) * 4;
    const float* W = (mat == 0) ? Wl1 : (mat == 1) ? Wr1 : (mat == 2) ? Wl2 : Wr2;
    float4 v;
    v.x = W[(cg + 0) * D + n];
    v.y = W[(cg + 1) * D + n];
    v.z = W[(cg + 2) * D + n];
    v.w = W[(cg + 3) * D + n];
    __half2 p01 = __floats2half2_rn(v.x, v.y);
    __half2 p23 = __floats2half2_rn(v.z, v.w);
    uint2 u;
    u.x = *(uint32_t*)&p01; u.y = *(uint32_t*)&p23;
    *(uint2*)(g_wt + (size_t)mat * D * D + (size_t)n * D + cg) = u;
}

// ---------------------------------------------------------------------------
// mma.sync fp16 2-term split dual-GEMM, GT=128 (R12-proven, unchanged).
// ---------------------------------------------------------------------------
#define AHI_OFF 0
#define ALO_OFF (GT * AST)                 // 17408
#define B_OFF   (2 * GT * AST)             // 34816
#define BIMG    (D * AST)                  // 17408
#define GSMEM_ELEMS (B_OFF + 2 * BIMG)     // 69632 fp16
#define GSMEM_BYTES (GSMEM_ELEMS * 2)      // 139264 B

__global__ __launch_bounds__(256, 1) void gemm_tc_kernel(
    const float* __restrict__ x_ext, int layer, int M, int tile0)
{
    extern __shared__ __half sm[];
    uint32_t sb = smem_u32(sm);
    const float* __restrict__ A = (layer == 0) ? x_ext : g_h;
    __half* __restrict__ xl_out = g_xl_h[layer];
    float*  __restrict__ xr_out = g_xr[layer];

    int tid = threadIdx.x;
    int wid = tid >> 5, l = tid & 31;
    int row0 = (tile0 + blockIdx.x) * GT;

    // ---- load A tile 128x128 fp32 -> fp16 hi/lo smem ----
    {
        int r = tid >> 1;                    // 0..127
        int cb = (tid & 1) * 64;
        int gr = row0 + r;
#pragma unroll
        for (int i = 0; i < 16; i++) {
            float4 v = make_float4(0.f, 0.f, 0.f, 0.f);
            if (gr < M) v = *(const float4*)(A + (size_t)gr * D + cb + i * 4);
            uint2 uhi, ulo;
            split_pack_h(v, uhi, ulo);
            *(uint2*)(sm + AHI_OFF + r * AST + cb + i * 4) = uhi;
            *(uint2*)(sm + ALO_OFF + r * AST + cb + i * 4) = ulo;
        }
    }
    // ---- load 2 weight images (layer-selected: Wl, Wr) into padded smem ----
    {
#pragma unroll
        for (int it = 0; it < 16; it++) {
            int idx = tid + it * 256;            // 0..4095
            int img = idx >> 11;                 // 0..1
            int rem = idx & 2047;
            int row = rem >> 4;
            int q   = rem & 15;
            const __half* src = g_wt + ((size_t)(layer * 2 + img) * D * D);
            uint4 v = ((const uint4*)(src + (size_t)row * D))[q];
            *(uint4*)(sm + B_OFF + img * BIMG + row * AST + q * 8) = v;
        }
    }
    __syncthreads();

    int mat = wid >> 2;                  // 0: Wl, 1: Wr
    int w = wid & 3;
    int wm = (w >> 1) * 64;
    int wn = (w & 1) * 64;

    uint32_t aHi[4], aLo[4];
#pragma unroll
    for (int mi = 0; mi < 4; mi++) {
        int ar = wm + mi * 16 + (l & 7) + ((l >> 3) & 1) * 8;
        int ac = ((l >> 4) & 1) * 8;
        aHi[mi] = sb + (uint32_t)(AHI_OFF + ar * AST + ac) * 2;
        aLo[mi] = sb + (uint32_t)(ALO_OFF + ar * AST + ac) * 2;
    }
    uint32_t bAddr[4];
#pragma unroll
    for (int jp = 0; jp < 4; jp++) {
        int br = wn + jp * 16 + (l & 7) + ((l >> 4) & 1) * 8;
        int bc = ((l >> 3) & 1) * 8;
        bAddr[jp] = sb + (uint32_t)(B_OFF + mat * BIMG + br * AST + bc) * 2;
    }

    float acc[4][8][4];
#pragma unroll
    for (int mi = 0; mi < 4; mi++)
#pragma unroll
        for (int nj = 0; nj < 8; nj++)
#pragma unroll
            for (int q = 0; q < 4; q++) acc[mi][nj][q] = 0.f;

#pragma unroll 1
    for (int ks = 0; ks < 8; ks++) {
        uint32_t kb = ks * 32;
        uint32_t ah[4][4], al[4][4], bh[8][2];
#pragma unroll
        for (int mi = 0; mi < 4; mi++) {
            LDSM4(ah[mi][0], ah[mi][1], ah[mi][2], ah[mi][3], aHi[mi] + kb);
            LDSM4(al[mi][0], al[mi][1], al[mi][2], al[mi][3], aLo[mi] + kb);
        }
#pragma unroll
        for (int jp = 0; jp < 4; jp++) {
            uint32_t r0, r1, r2, r3;
            LDSM4(r0, r1, r2, r3, bAddr[jp] + kb);
            bh[2 * jp][0] = r0; bh[2 * jp][1] = r1;
            bh[2 * jp + 1][0] = r2; bh[2 * jp + 1][1] = r3;
        }
#pragma unroll
        for (int mi = 0; mi < 4; mi++)
#pragma unroll
            for (int nj = 0; nj < 8; nj++) {
                MMA16816(acc[mi][nj], ah[mi], bh[nj]);
                MMA16816(acc[mi][nj], al[mi], bh[nj]);
            }
    }

    // ---- epilogue ----
    int g = l >> 2, t4 = l & 3;
#pragma unroll
    for (int mi = 0; mi < 4; mi++) {
        int r0 = row0 + wm + mi * 16 + g;
        int r1 = r0 + 8;
#pragma unroll
        for (int nj = 0; nj < 8; nj++) {
            int col = wn + nj * 8 + t4 * 2;
            if (mat == 0) {
                if (r0 < M) {
                    __half2 p = __floats2half2_rn(acc[mi][nj][0], acc[mi][nj][1]);
                    *(__half2*)(xl_out + (size_t)r0 * D + col) = p;
                }
                if (r1 < M) {
                    __half2 p = __floats2half2_rn(acc[mi][nj][2], acc[mi][nj][3]);
                    *(__half2*)(xl_out + (size_t)r1 * D + col) = p;
                }
            } else {
                if (r0 < M)
                    *(float2*)(xr_out + (size_t)r0 * D + col) =
                        make_float2(acc[mi][nj][0], acc[mi][nj][1]);
                if (r1 < M)
                    *(float2*)(xr_out + (size_t)r1 * D + col) =
                        make_float2(acc[mi][nj][2], acc[mi][nj][3]);
            }
        }
    }
}

// ---------------------------------------------------------------------------
// Fused aggregate + epilogue v2: one warp per dst node.
// Lanes 0-15 gather edge i, lanes 16-31 edge i+1 — each lane LDG.128 (16B),
// one LDG warp-instruction per TWO edges. Final shfl.xor(16) merges halves.
// ---------------------------------------------------------------------------
__device__ __forceinline__ void add8(float* acc, uint4 v) {
    float2 f0 = __half22float2(*(__half2*)&v.x);
    float2 f1 = __half22float2(*(__half2*)&v.y);
    float2 f2 = __half22float2(*(__half2*)&v.z);
    float2 f3 = __half22float2(*(__half2*)&v.w);
    acc[0] += f0.x; acc[1] += f0.y; acc[2] += f1.x; acc[3] += f1.y;
    acc[4] += f2.x; acc[5] += f2.y; acc[6] += f3.x; acc[7] += f3.y;
}

__global__ __launch_bounds__(256) void agg_finish_kernel(
    const float* __restrict__ b, float* __restrict__ out_ext,
    int layer, int n0, int n1)
{
    long long t = (long long)blockIdx.x * blockDim.x + threadIdx.x;
    int n = n0 + (int)(t >> 5);
    if (n >= n1) return;                    // whole warp exits together
    int l = (int)t & 31;
    int c8 = (l & 15) * 8;                  // 8 halfs = 16 bytes per lane
    int sel = l >> 4;                       // half-warp: which edge of pair

    const __half* __restrict__ xl = g_xl_h[layer];

    float acc[8];
#pragma unroll
    for (int q = 0; q < 8; q++) acc[q] = 0.f;

    int s = g_rowptr[n], e = g_rowptr[n + 1];
    int i = s;
    for (; i + 7 < e; i += 8) {             // 8 edges per iter: 4 pair-loads
#pragma unroll
        for (int u = 0; u < 4; u++) {
            int src = g_srcs[i + 2 * u + sel];
            uint4 v = *(const uint4*)(xl + (size_t)src * D + c8);
            add8(acc, v);
        }
    }
    for (; i < e; i += 2) {                 // tail: predicated pair
        int e0 = i + sel;
        if (e0 < e) {
            int src = g_srcs[e0];
            uint4 v = *(const uint4*)(xl + (size_t)src * D + c8);
            add8(acc, v);
        }
    }

    // merge the two half-warp partial sums
#pragma unroll
    for (int q = 0; q < 8; q++)
        acc[q] += __shfl_xor_sync(0xFFFFFFFFu, acc[q], 16);

    if (sel == 0) {
        float inv = g_inv[n];
        const float* xrb = g_xr[layer] + (size_t)n * D + c8;
        float4 xr0 = *(const float4*)(xrb);
        float4 xr1 = *(const float4*)(xrb + 4);
        float4 b0 = *(const float4*)(b + c8);
        float4 b1 = *(const float4*)(b + c8 + 4);
        float4 r0, r1;
        r0.x = fmaxf(fmaf(acc[0], inv, xr0.x + b0.x), 0.f);
        r0.y = fmaxf(fmaf(acc[1], inv, xr0.y + b0.y), 0.f);
        r0.z = fmaxf(fmaf(acc[2], inv, xr0.z + b0.z), 0.f);
        r0.w = fmaxf(fmaf(acc[3], inv, xr0.w + b0.w), 0.f);
        r1.x = fmaxf(fmaf(acc[4], inv, xr1.x + b1.x), 0.f);
        r1.y = fmaxf(fmaf(acc[5], inv, xr1.y + b1.y), 0.f);
        r1.z = fmaxf(fmaf(acc[6], inv, xr1.z + b1.z), 0.f);
        r1.w = fmaxf(fmaf(acc[7], inv, xr1.w + b1.w), 0.f);
        float* dst = ((layer == 0) ? g_h : out_ext) + (size_t)n * D + c8;
        *(float4*)dst = r0;
        *(float4*)(dst + 4) = r1;
    }
}

// ---------------------------------------------------------------------------
extern "C" void kernel_launch(void* const* d_in, const int* in_sizes, int n_in,
                              void* d_out, int out_size) {
    const float* x    = (const float*)d_in[0];
    const int*   ei   = (const int*)d_in[1];
    const float* W_l1 = (const float*)d_in[2];
    const float* W_r1 = (const float*)d_in[3];
    const float* b1   = (const float*)d_in[4];
    const float* W_l2 = (const float*)d_in[5];
    const float* W_r2 = (const float*)d_in[6];
    const float* b2   = (const float*)d_in[7];
    float* out        = (float*)d_out;

    int N = in_sizes[0] / D;   // 100000
    int E = in_sizes[1] / 2;   // 1600000

    // One-time resource setup on the first (correctness) call — before the
    // harness's pre-capture baseline. Capture call creates nothing.
    static cudaStream_t s1 = nullptr, s2 = nullptr;
    static cudaEvent_t evFork = nullptr, evCsr = nullptr, evW = nullptr, evG = nullptr;
    static cudaEvent_t evA[4] = {nullptr, nullptr, nullptr, nullptr};
    if (s1 == nullptr) {
        cudaStreamCreateWithFlags(&s1, cudaStreamNonBlocking);
        cudaStreamCreateWithFlags(&s2, cudaStreamNonBlocking);
        cudaEventCreateWithFlags(&evFork, cudaEventDisableTiming);
        cudaEventCreateWithFlags(&evCsr, cudaEventDisableTiming);
        cudaEventCreateWithFlags(&evW, cudaEventDisableTiming);
        cudaEventCreateWithFlags(&evG, cudaEventDisableTiming);
        for (int k = 0; k < 4; k++)
            cudaEventCreateWithFlags(&evA[k], cudaEventDisableTiming);
        cudaFuncSetAttribute(gemm_tc_kernel,
                             cudaFuncAttributeMaxDynamicSharedMemorySize, GSMEM_BYTES);
    }

    int tb = 256;
    int grid_N    = (N + tb - 1) / tb;
    int grid_E    = (E + tb - 1) / tb;
    int tiles     = (N + GT - 1) / GT;               // 782
    int tq        = (tiles + 3) / 4;                 // 196 tiles per chunk
    int NQ        = tq * GT;                         // 25088 nodes per chunk
    int nblocks_scan = (N + SCH - 1) / SCH;

    auto agrid = [tb](int cnt) { return (int)(((long long)cnt * 32 + tb - 1) / tb); };

    cudaEventRecord(evFork, 0);

    // s1: CSR build (depends only on edge_index)
    cudaStreamWaitEvent(s1, evFork, 0);
    zero_cnt_kernel<<<grid_N, tb, 0, s1>>>(N);
    hist_kernel<<<grid_E, tb, 0, s1>>>(ei, E);
    scan1_kernel<<<nblocks_scan, SCH, 0, s1>>>(N);
    scan2_kernel<<<1, 256, 0, s1>>>(nblocks_scan);
    scan3_kernel<<<grid_N, tb, 0, s1>>>(N);
    fill_kernel<<<grid_E, tb, 0, s1>>>(ei, E);
    cudaEventRecord(evCsr, s1);

    // s2: weight transpose to fp16
    cudaStreamWaitEvent(s2, evFork, 0);
    wtrans_kernel<<<64, 256, 0, s2>>>(W_l1, W_r1, W_l2, W_r2);
    cudaEventRecord(evW, s2);

    // Layer 1 GEMM (full), CSR hidden behind it
    cudaStreamWaitEvent(0, evW, 0);
    gemm_tc_kernel<<<tiles, 256, GSMEM_BYTES>>>(x, 0, N, 0);

    // agg1 in 4 chunks on main || gemm2 chunks trail on s2.
    // gemm2 writes xl[1]/xr[1]; agg1 reads xl[0]/xr[0] — disjoint buffers.
    // gemm2 chunk k reads exactly g_h rows produced by agg1 chunk k.
    cudaStreamWaitEvent(0, evCsr, 0);
    for (int k = 0; k < 4; k++) {
        int a0 = k * NQ, a1 = (k == 3) ? N : (k + 1) * NQ;
        agg_finish_kernel<<<agrid(a1 - a0), tb>>>(b1, out, 0, a0, a1);
        cudaEventRecord(evA[k], 0);
        cudaStreamWaitEvent(s2, evA[k], 0);
        int t0 = k * tq, t1 = (k == 3) ? tiles : (k + 1) * tq;
        gemm_tc_kernel<<<t1 - t0, 256, GSMEM_BYTES, s2>>>(x, 1, N, t0);
    }
    cudaEventRecord(evG, s2);

    // Layer 2 aggregation needs all gemm2 chunks
    cudaStreamWaitEvent(0, evG, 0);
    agg_finish_kernel<<<agrid(N), tb>>>(b2, out, 1, 0, N);
}

// round 15
// speedup vs baseline: 1.0439x; 1.0439x over previous
#include <cuda_runtime.h>
#include <cuda_fp16.h>
#include <cstdint>

#define D 128
#define NMAX 100000
#define EMAX 1600000
#define SCH 512
#define GT 128                // gemm M tile
#define AST 136               // padded smem row stride (fp16 elems)

// Scratch (device globals — no runtime allocation allowed)
// xl / xr double-buffered per layer (race-free gemm2 || agg1 overlap).
__device__ __half g_xl_h[2][(size_t)NMAX * D]; // A @ W_l (fp16, gather-only)
__device__ float  g_xr[2][(size_t)NMAX * D];   // A @ W_r
__device__ float  g_h [(size_t)NMAX * D];      // layer-1 output
__device__ __half g_wt[4 * D * D];             // W^T fp16: Wl1,Wr1,Wl2,Wr2 ([n][k] row-major)
__device__ float  g_inv[NMAX];
__device__ int    g_cnt[NMAX];
__device__ int    g_fill[NMAX];
__device__ int    g_rowptr[NMAX + 1];
__device__ int    g_srcs[EMAX];
__device__ int    g_bsum[256];

// ---------------------------------------------------------------------------
__device__ __forceinline__ uint32_t smem_u32(const void* p) {
    uint32_t a;
    asm("{ .reg .u64 t; cvta.to.shared.u64 t, %1; cvt.u32.u64 %0, t; }" : "=r"(a) : "l"(p));
    return a;
}
// fp16 hi/lo split: x = hi + lo with |residual| ~ 6e-8 relative
__device__ __forceinline__ void split_pack_h(const float4 v, uint2& uhi, uint2& ulo) {
    __half2 h01 = __floats2half2_rn(v.x, v.y);
    __half2 h23 = __floats2half2_rn(v.z, v.w);
    float2 f01 = __half22float2(h01), f23 = __half22float2(h23);
    __half2 l01 = __floats2half2_rn(v.x - f01.x, v.y - f01.y);
    __half2 l23 = __floats2half2_rn(v.z - f23.x, v.w - f23.y);
    uhi.x = *(uint32_t*)&h01; uhi.y = *(uint32_t*)&h23;
    ulo.x = *(uint32_t*)&l01; ulo.y = *(uint32_t*)&l23;
}
#define LDSM4(r0, r1, r2, r3, a) \
    asm volatile("ldmatrix.sync.aligned.m8n8.x4.shared.b16 {%0,%1,%2,%3}, [%4];" \
                 : "=r"(r0), "=r"(r1), "=r"(r2), "=r"(r3) : "r"(a))
#define MMA16816(c, a, b) \
    asm volatile("mma.sync.aligned.m16n8k16.row.col.f32.f16.f16.f32 " \
                 "{%0,%1,%2,%3}, {%4,%5,%6,%7}, {%8,%9}, {%0,%1,%2,%3};" \
                 : "+f"((c)[0]), "+f"((c)[1]), "+f"((c)[2]), "+f"((c)[3]) \
                 : "r"((a)[0]), "r"((a)[1]), "r"((a)[2]), "r"((a)[3]), \
                   "r"((b)[0]), "r"((b)[1]))

// ---------------------------------------------------------------------------
// CSR build
// ---------------------------------------------------------------------------
__global__ void zero_cnt_kernel(int N) {
    int i = blockIdx.x * blockDim.x + threadIdx.x;
    if (i < N) g_cnt[i] = 0;
}
__global__ void hist_kernel(const int* __restrict__ ei, int E) {
    int e = blockIdx.x * blockDim.x + threadIdx.x;
    if (e < E) atomicAdd(&g_cnt[ei[E + e]], 1);
}
__global__ __launch_bounds__(SCH) void scan1_kernel(int N) {
    __shared__ int sh[SCH];
    int t = threadIdx.x;
    int gi = blockIdx.x * SCH + t;
    sh[t] = (gi < N) ? g_cnt[gi] : 0;
    __syncthreads();
#pragma unroll
    for (int off = 1; off < SCH; off <<= 1) {
        int y = (t >= off) ? sh[t - off] : 0;
        __syncthreads();
        sh[t] += y;
        __syncthreads();
    }
    if (gi < N) g_rowptr[gi + 1] = sh[t];
    if (t == SCH - 1) g_bsum[blockIdx.x] = sh[t];
}
__global__ __launch_bounds__(256) void scan2_kernel(int nblocks) {
    __shared__ int sh[256];
    int t = threadIdx.x;
    sh[t] = (t < nblocks) ? g_bsum[t] : 0;
    __syncthreads();
#pragma unroll
    for (int off = 1; off < 256; off <<= 1) {
        int y = (t >= off) ? sh[t - off] : 0;
        __syncthreads();
        sh[t] += y;
        __syncthreads();
    }
    if (t < nblocks) g_bsum[t] = (t > 0) ? sh[t - 1] : 0;
}
__global__ void scan3_kernel(int N) {
    int i = blockIdx.x * blockDim.x + threadIdx.x;
    if (i >= N) return;
    int incl = g_rowptr[i + 1] + g_bsum[i / SCH];
    g_rowptr[i + 1] = incl;
    g_inv[i] = 1.0f / fmaxf((float)g_cnt[i], 1.0f);
    g_fill[i] = incl - g_cnt[i];   // cursor starts at rowptr[i]
    if (i == 0) g_rowptr[0] = 0;
}
__global__ void fill_kernel(const int* __restrict__ ei, int E) {
    int e = blockIdx.x * blockDim.x + threadIdx.x;
    if (e >= E) return;
    int d = ei[E + e];
    int pos = atomicAdd(&g_fill[d], 1);
    g_srcs[pos] = ei[e];
}

// ---------------------------------------------------------------------------
// wtrans: W[k][n] fp32 -> W^T[n][k] fp16 (4 matrices, row-major)
// ---------------------------------------------------------------------------
__global__ __launch_bounds__(256) void wtrans_kernel(
    const float* __restrict__ Wl1, const float* __restrict__ Wr1,
    const float* __restrict__ Wl2, const float* __restrict__ Wr2)
{
    int t = blockIdx.x * blockDim.x + threadIdx.x;   // 0 .. 16383
    int mat = t >> 12;
    int rem = t & 4095;
    int n = rem >> 5;
    int cg = (rem & 31) * 4;
    const float* W = (mat == 0) ? Wl1 : (mat == 1) ? Wr1 : (mat == 2) ? Wl2 : Wr2;
    float4 v;
    v.x = W[(cg + 0) * D + n];
    v.y = W[(cg + 1) * D + n];
    v.z = W[(cg + 2) * D + n];
    v.w = W[(cg + 3) * D + n];
    __half2 p01 = __floats2half2_rn(v.x, v.y);
    __half2 p23 = __floats2half2_rn(v.z, v.w);
    uint2 u;
    u.x = *(uint32_t*)&p01; u.y = *(uint32_t*)&p23;
    *(uint2*)(g_wt + (size_t)mat * D * D + (size_t)n * D + cg) = u;
}

// ---------------------------------------------------------------------------
// mma.sync fp16 2-term split dual-GEMM, GT=128 (R12-proven, unchanged).
// ---------------------------------------------------------------------------
#define AHI_OFF 0
#define ALO_OFF (GT * AST)                 // 17408
#define B_OFF   (2 * GT * AST)             // 34816
#define BIMG    (D * AST)                  // 17408
#define GSMEM_ELEMS (B_OFF + 2 * BIMG)     // 69632 fp16
#define GSMEM_BYTES (GSMEM_ELEMS * 2)      // 139264 B

__global__ __launch_bounds__(256, 1) void gemm_tc_kernel(
    const float* __restrict__ x_ext, int layer, int M, int tile0)
{
    extern __shared__ __half sm[];
    uint32_t sb = smem_u32(sm);
    const float* __restrict__ A = (layer == 0) ? x_ext : g_h;
    __half* __restrict__ xl_out = g_xl_h[layer];
    float*  __restrict__ xr_out = g_xr[layer];

    int tid = threadIdx.x;
    int wid = tid >> 5, l = tid & 31;
    int row0 = (tile0 + blockIdx.x) * GT;

    // ---- load A tile 128x128 fp32 -> fp16 hi/lo smem ----
    {
        int r = tid >> 1;                    // 0..127
        int cb = (tid & 1) * 64;
        int gr = row0 + r;
#pragma unroll
        for (int i = 0; i < 16; i++) {
            float4 v = make_float4(0.f, 0.f, 0.f, 0.f);
            if (gr < M) v = *(const float4*)(A + (size_t)gr * D + cb + i * 4);
            uint2 uhi, ulo;
            split_pack_h(v, uhi, ulo);
            *(uint2*)(sm + AHI_OFF + r * AST + cb + i * 4) = uhi;
            *(uint2*)(sm + ALO_OFF + r * AST + cb + i * 4) = ulo;
        }
    }
    // ---- load 2 weight images (layer-selected: Wl, Wr) into padded smem ----
    {
#pragma unroll
        for (int it = 0; it < 16; it++) {
            int idx = tid + it * 256;            // 0..4095
            int img = idx >> 11;                 // 0..1
            int rem = idx & 2047;
            int row = rem >> 4;
            int q   = rem & 15;
            const __half* src = g_wt + ((size_t)(layer * 2 + img) * D * D);
            uint4 v = ((const uint4*)(src + (size_t)row * D))[q];
            *(uint4*)(sm + B_OFF + img * BIMG + row * AST + q * 8) = v;
        }
    }
    __syncthreads();

    int mat = wid >> 2;                  // 0: Wl, 1: Wr
    int w = wid & 3;
    int wm = (w >> 1) * 64;
    int wn = (w & 1) * 64;

    uint32_t aHi[4], aLo[4];
#pragma unroll
    for (int mi = 0; mi < 4; mi++) {
        int ar = wm + mi * 16 + (l & 7) + ((l >> 3) & 1) * 8;
        int ac = ((l >> 4) & 1) * 8;
        aHi[mi] = sb + (uint32_t)(AHI_OFF + ar * AST + ac) * 2;
        aLo[mi] = sb + (uint32_t)(ALO_OFF + ar * AST + ac) * 2;
    }
    uint32_t bAddr[4];
#pragma unroll
    for (int jp = 0; jp < 4; jp++) {
        int br = wn + jp * 16 + (l & 7) + ((l >> 4) & 1) * 8;
        int bc = ((l >> 3) & 1) * 8;
        bAddr[jp] = sb + (uint32_t)(B_OFF + mat * BIMG + br * AST + bc) * 2;
    }

    float acc[4][8][4];
#pragma unroll
    for (int mi = 0; mi < 4; mi++)
#pragma unroll
        for (int nj = 0; nj < 8; nj++)
#pragma unroll
            for (int q = 0; q < 4; q++) acc[mi][nj][q] = 0.f;

#pragma unroll 1
    for (int ks = 0; ks < 8; ks++) {
        uint32_t kb = ks * 32;
        uint32_t ah[4][4], al[4][4], bh[8][2];
#pragma unroll
        for (int mi = 0; mi < 4; mi++) {
            LDSM4(ah[mi][0], ah[mi][1], ah[mi][2], ah[mi][3], aHi[mi] + kb);
            LDSM4(al[mi][0], al[mi][1], al[mi][2], al[mi][3], aLo[mi] + kb);
        }
#pragma unroll
        for (int jp = 0; jp < 4; jp++) {
            uint32_t r0, r1, r2, r3;
            LDSM4(r0, r1, r2, r3, bAddr[jp] + kb);
            bh[2 * jp][0] = r0; bh[2 * jp][1] = r1;
            bh[2 * jp + 1][0] = r2; bh[2 * jp + 1][1] = r3;
        }
#pragma unroll
        for (int mi = 0; mi < 4; mi++)
#pragma unroll
            for (int nj = 0; nj < 8; nj++) {
                MMA16816(acc[mi][nj], ah[mi], bh[nj]);
                MMA16816(acc[mi][nj], al[mi], bh[nj]);
            }
    }

    // ---- epilogue ----
    int g = l >> 2, t4 = l & 3;
#pragma unroll
    for (int mi = 0; mi < 4; mi++) {
        int r0 = row0 + wm + mi * 16 + g;
        int r1 = r0 + 8;
#pragma unroll
        for (int nj = 0; nj < 8; nj++) {
            int col = wn + nj * 8 + t4 * 2;
            if (mat == 0) {
                if (r0 < M) {
                    __half2 p = __floats2half2_rn(acc[mi][nj][0], acc[mi][nj][1]);
                    *(__half2*)(xl_out + (size_t)r0 * D + col) = p;
                }
                if (r1 < M) {
                    __half2 p = __floats2half2_rn(acc[mi][nj][2], acc[mi][nj][3]);
                    *(__half2*)(xl_out + (size_t)r1 * D + col) = p;
                }
            } else {
                if (r0 < M)
                    *(float2*)(xr_out + (size_t)r0 * D + col) =
                        make_float2(acc[mi][nj][0], acc[mi][nj][1]);
                if (r1 < M)
                    *(float2*)(xr_out + (size_t)r1 * D + col) =
                        make_float2(acc[mi][nj][2], acc[mi][nj][3]);
            }
        }
    }
}

// ---------------------------------------------------------------------------
// Fused aggregate + epilogue (pair-edge v2): one warp per dst node.
// Lanes 0-15 gather edge i, lanes 16-31 edge i+1 — each lane LDG.128 (16B),
// one LDG warp-instruction per TWO edges. Final shfl.xor(16) merges halves.
// ---------------------------------------------------------------------------
__device__ __forceinline__ void add8(float* acc, uint4 v) {
    float2 f0 = __half22float2(*(__half2*)&v.x);
    float2 f1 = __half22float2(*(__half2*)&v.y);
    float2 f2 = __half22float2(*(__half2*)&v.z);
    float2 f3 = __half22float2(*(__half2*)&v.w);
    acc[0] += f0.x; acc[1] += f0.y; acc[2] += f1.x; acc[3] += f1.y;
    acc[4] += f2.x; acc[5] += f2.y; acc[6] += f3.x; acc[7] += f3.y;
}

__global__ __launch_bounds__(256) void agg_finish_kernel(
    const float* __restrict__ b, float* __restrict__ out_ext,
    int layer, int n0, int n1)
{
    long long t = (long long)blockIdx.x * blockDim.x + threadIdx.x;
    int n = n0 + (int)(t >> 5);
    if (n >= n1) return;                    // whole warp exits together
    int l = (int)t & 31;
    int c8 = (l & 15) * 8;                  // 8 halfs = 16 bytes per lane
    int sel = l >> 4;                       // half-warp: which edge of pair

    const __half* __restrict__ xl = g_xl_h[layer];

    float acc[8];
#pragma unroll
    for (int q = 0; q < 8; q++) acc[q] = 0.f;

    int s = g_rowptr[n], e = g_rowptr[n + 1];
    int i = s;
    for (; i + 7 < e; i += 8) {             // 8 edges per iter: 4 pair-loads
#pragma unroll
        for (int u = 0; u < 4; u++) {
            int src = g_srcs[i + 2 * u + sel];
            uint4 v = *(const uint4*)(xl + (size_t)src * D + c8);
            add8(acc, v);
        }
    }
    for (; i < e; i += 2) {                 // tail: predicated pair
        int e0 = i + sel;
        if (e0 < e) {
            int src = g_srcs[e0];
            uint4 v = *(const uint4*)(xl + (size_t)src * D + c8);
            add8(acc, v);
        }
    }

    // merge the two half-warp partial sums
#pragma unroll
    for (int q = 0; q < 8; q++)
        acc[q] += __shfl_xor_sync(0xFFFFFFFFu, acc[q], 16);

    if (sel == 0) {
        float inv = g_inv[n];
        const float* xrb = g_xr[layer] + (size_t)n * D + c8;
        float4 xr0 = *(const float4*)(xrb);
        float4 xr1 = *(const float4*)(xrb + 4);
        float4 b0 = *(const float4*)(b + c8);
        float4 b1 = *(const float4*)(b + c8 + 4);
        float4 r0, r1;
        r0.x = fmaxf(fmaf(acc[0], inv, xr0.x + b0.x), 0.f);
        r0.y = fmaxf(fmaf(acc[1], inv, xr0.y + b0.y), 0.f);
        r0.z = fmaxf(fmaf(acc[2], inv, xr0.z + b0.z), 0.f);
        r0.w = fmaxf(fmaf(acc[3], inv, xr0.w + b0.w), 0.f);
        r1.x = fmaxf(fmaf(acc[4], inv, xr1.x + b1.x), 0.f);
        r1.y = fmaxf(fmaf(acc[5], inv, xr1.y + b1.y), 0.f);
        r1.z = fmaxf(fmaf(acc[6], inv, xr1.z + b1.z), 0.f);
        r1.w = fmaxf(fmaf(acc[7], inv, xr1.w + b1.w), 0.f);
        float* dst = ((layer == 0) ? g_h : out_ext) + (size_t)n * D + c8;
        *(float4*)dst = r0;
        *(float4*)(dst + 4) = r1;
    }
}

// ---------------------------------------------------------------------------
extern "C" void kernel_launch(void* const* d_in, const int* in_sizes, int n_in,
                              void* d_out, int out_size) {
    const float* x    = (const float*)d_in[0];
    const int*   ei   = (const int*)d_in[1];
    const float* W_l1 = (const float*)d_in[2];
    const float* W_r1 = (const float*)d_in[3];
    const float* b1   = (const float*)d_in[4];
    const float* W_l2 = (const float*)d_in[5];
    const float* W_r2 = (const float*)d_in[6];
    const float* b2   = (const float*)d_in[7];
    float* out        = (float*)d_out;

    int N = in_sizes[0] / D;   // 100000
    int E = in_sizes[1] / 2;   // 1600000

    // One-time resource setup on the first (correctness) call — before the
    // harness's pre-capture baseline. Capture call creates nothing.
    static cudaStream_t s1 = nullptr, s2 = nullptr;
    static cudaEvent_t evFork = nullptr, evCsr = nullptr, evW = nullptr,
                       evA0 = nullptr, evG0 = nullptr;
    if (s1 == nullptr) {
        cudaStreamCreateWithFlags(&s1, cudaStreamNonBlocking);
        cudaStreamCreateWithFlags(&s2, cudaStreamNonBlocking);
        cudaEventCreateWithFlags(&evFork, cudaEventDisableTiming);
        cudaEventCreateWithFlags(&evCsr, cudaEventDisableTiming);
        cudaEventCreateWithFlags(&evW, cudaEventDisableTiming);
        cudaEventCreateWithFlags(&evA0, cudaEventDisableTiming);
        cudaEventCreateWithFlags(&evG0, cudaEventDisableTiming);
        cudaFuncSetAttribute(gemm_tc_kernel,
                             cudaFuncAttributeMaxDynamicSharedMemorySize, GSMEM_BYTES);
    }

    int tb = 256;
    int grid_N    = (N + tb - 1) / tb;
    int grid_E    = (E + tb - 1) / tb;
    int tiles     = (N + GT - 1) / GT;               // 782
    int tiles0    = tiles / 2;                       // 391
    int NH        = tiles0 * GT;                     // 50048
    int nblocks_scan = (N + SCH - 1) / SCH;

    auto agrid = [tb](int cnt) { return (int)(((long long)cnt * 32 + tb - 1) / tb); };

    cudaEventRecord(evFork, 0);

    // s1: CSR build (depends only on edge_index)
    cudaStreamWaitEvent(s1, evFork, 0);
    zero_cnt_kernel<<<grid_N, tb, 0, s1>>>(N);
    hist_kernel<<<grid_E, tb, 0, s1>>>(ei, E);
    scan1_kernel<<<nblocks_scan, SCH, 0, s1>>>(N);
    scan2_kernel<<<1, 256, 0, s1>>>(nblocks_scan);
    scan3_kernel<<<grid_N, tb, 0, s1>>>(N);
    fill_kernel<<<grid_E, tb, 0, s1>>>(ei, E);
    cudaEventRecord(evCsr, s1);

    // s2: weight transpose to fp16
    cudaStreamWaitEvent(s2, evFork, 0);
    wtrans_kernel<<<64, 256, 0, s2>>>(W_l1, W_r1, W_l2, W_r2);
    cudaEventRecord(evW, s2);

    // Layer 1 GEMM (full), CSR hidden behind it
    cudaStreamWaitEvent(0, evW, 0);
    gemm_tc_kernel<<<tiles, 256, GSMEM_BYTES>>>(x, 0, N, 0);

    // R12 structure: agg1 on C0, then gemm2(C0) on s2 || agg1(C1) on main.
    // gemm2 writes xl[1]/xr[1]; agg1 reads xl[0]/xr[0] — disjoint buffers.
    cudaStreamWaitEvent(0, evCsr, 0);
    agg_finish_kernel<<<agrid(NH), tb>>>(b1, out, 0, 0, NH);
    cudaEventRecord(evA0, 0);

    cudaStreamWaitEvent(s2, evA0, 0);
    gemm_tc_kernel<<<tiles0, 256, GSMEM_BYTES, s2>>>(x, 1, N, 0);
    cudaEventRecord(evG0, s2);

    agg_finish_kernel<<<agrid(N - NH), tb>>>(b1, out, 0, NH, N);
    gemm_tc_kernel<<<tiles - tiles0, 256, GSMEM_BYTES>>>(x, 1, N, tiles0);

    // Layer 2 aggregation needs both gemm2 halves
    cudaStreamWaitEvent(0, evG0, 0);
    agg_finish_kernel<<<agrid(N), tb>>>(b2, out, 1, 0, N);
}

// round 16
// speedup vs baseline: 1.1254x; 1.0781x over previous
#include <cuda_runtime.h>
#include <cuda_fp16.h>
#include <cstdint>

#define D 128
#define NMAX 100000
#define EMAX 1600000
#define SCH 512
#define GT 64                 // gemm M tile (2 CTAs/SM)
#define AST 136               // padded smem row stride (fp16 elems)

// Scratch (device globals — no runtime allocation allowed)
// xl / xr double-buffered per layer (race-free gemm2 || agg1 overlap).
__device__ __half g_xl_h[2][(size_t)NMAX * D]; // A @ W_l (fp16, gather-only)
__device__ float  g_xr[2][(size_t)NMAX * D];   // A @ W_r
__device__ float  g_h [(size_t)NMAX * D];      // layer-1 output
__device__ __half g_wt[4 * D * D];             // W^T fp16: Wl1,Wr1,Wl2,Wr2 ([n][k] row-major)
__device__ float  g_inv[NMAX];
__device__ int    g_cnt[NMAX];
__device__ int    g_fill[NMAX];
__device__ int    g_rowptr[NMAX + 1];
__device__ int    g_srcs[EMAX];
__device__ int    g_bsum[256];

// ---------------------------------------------------------------------------
__device__ __forceinline__ uint32_t smem_u32(const void* p) {
    uint32_t a;
    asm("{ .reg .u64 t; cvta.to.shared.u64 t, %1; cvt.u32.u64 %0, t; }" : "=r"(a) : "l"(p));
    return a;
}
// fp16 hi/lo split: x = hi + lo with |residual| ~ 6e-8 relative
__device__ __forceinline__ void split_pack_h(const float4 v, uint2& uhi, uint2& ulo) {
    __half2 h01 = __floats2half2_rn(v.x, v.y);
    __half2 h23 = __floats2half2_rn(v.z, v.w);
    float2 f01 = __half22float2(h01), f23 = __half22float2(h23);
    __half2 l01 = __floats2half2_rn(v.x - f01.x, v.y - f01.y);
    __half2 l23 = __floats2half2_rn(v.z - f23.x, v.w - f23.y);
    uhi.x = *(uint32_t*)&h01; uhi.y = *(uint32_t*)&h23;
    ulo.x = *(uint32_t*)&l01; ulo.y = *(uint32_t*)&l23;
}
#define LDSM4(r0, r1, r2, r3, a) \
    asm volatile("ldmatrix.sync.aligned.m8n8.x4.shared.b16 {%0,%1,%2,%3}, [%4];" \
                 : "=r"(r0), "=r"(r1), "=r"(r2), "=r"(r3) : "r"(a))
#define MMA16816(c, a, b) \
    asm volatile("mma.sync.aligned.m16n8k16.row.col.f32.f16.f16.f32 " \
                 "{%0,%1,%2,%3}, {%4,%5,%6,%7}, {%8,%9}, {%0,%1,%2,%3};" \
                 : "+f"((c)[0]), "+f"((c)[1]), "+f"((c)[2]), "+f"((c)[3]) \
                 : "r"((a)[0]), "r"((a)[1]), "r"((a)[2]), "r"((a)[3]), \
                   "r"((b)[0]), "r"((b)[1]))

// ---------------------------------------------------------------------------
// CSR build
// ---------------------------------------------------------------------------
__global__ void zero_cnt_kernel(int N) {
    int i = blockIdx.x * blockDim.x + threadIdx.x;
    if (i < N) g_cnt[i] = 0;
}
__global__ void hist_kernel(const int* __restrict__ ei, int E) {
    int e = blockIdx.x * blockDim.x + threadIdx.x;
    if (e < E) atomicAdd(&g_cnt[ei[E + e]], 1);
}
__global__ __launch_bounds__(SCH) void scan1_kernel(int N) {
    __shared__ int sh[SCH];
    int t = threadIdx.x;
    int gi = blockIdx.x * SCH + t;
    sh[t] = (gi < N) ? g_cnt[gi] : 0;
    __syncthreads();
#pragma unroll
    for (int off = 1; off < SCH; off <<= 1) {
        int y = (t >= off) ? sh[t - off] : 0;
        __syncthreads();
        sh[t] += y;
        __syncthreads();
    }
    if (gi < N) g_rowptr[gi + 1] = sh[t];
    if (t == SCH - 1) g_bsum[blockIdx.x] = sh[t];
}
__global__ __launch_bounds__(256) void scan2_kernel(int nblocks) {
    __shared__ int sh[256];
    int t = threadIdx.x;
    sh[t] = (t < nblocks) ? g_bsum[t] : 0;
    __syncthreads();
#pragma unroll
    for (int off = 1; off < 256; off <<= 1) {
        int y = (t >= off) ? sh[t - off] : 0;
        __syncthreads();
        sh[t] += y;
        __syncthreads();
    }
    if (t < nblocks) g_bsum[t] = (t > 0) ? sh[t - 1] : 0;
}
__global__ void scan3_kernel(int N) {
    int i = blockIdx.x * blockDim.x + threadIdx.x;
    if (i >= N) return;
    int incl = g_rowptr[i + 1] + g_bsum[i / SCH];
    g_rowptr[i + 1] = incl;
    g_inv[i] = 1.0f / fmaxf((float)g_cnt[i], 1.0f);
    g_fill[i] = incl - g_cnt[i];   // cursor starts at rowptr[i]
    if (i == 0) g_rowptr[0] = 0;
}
__global__ void fill_kernel(const int* __restrict__ ei, int E) {
    int e = blockIdx.x * blockDim.x + threadIdx.x;
    if (e >= E) return;
    int d = ei[E + e];
    int pos = atomicAdd(&g_fill[d], 1);
    g_srcs[pos] = ei[e];
}

// ---------------------------------------------------------------------------
// wtrans: W[k][n] fp32 -> W^T[n][k] fp16 (4 matrices, row-major)
// ---------------------------------------------------------------------------
__global__ __launch_bounds__(256) void wtrans_kernel(
    const float* __restrict__ Wl1, const float* __restrict__ Wr1,
    const float* __restrict__ Wl2, const float* __restrict__ Wr2)
{
    int t = blockIdx.x * blockDim.x + threadIdx.x;   // 0 .. 16383
    int mat = t >> 12;
    int rem = t & 4095;
    int n = rem >> 5;
    int cg = (rem & 31) * 4;
    const float* W = (mat == 0) ? Wl1 : (mat == 1) ? Wr1 : (mat == 2) ? Wl2 : Wr2;
    float4 v;
    v.x = W[(cg + 0) * D + n];
    v.y = W[(cg + 1) * D + n];
    v.z = W[(cg + 2) * D + n];
    v.w = W[(cg + 3) * D + n];
    __half2 p01 = __floats2half2_rn(v.x, v.y);
    __half2 p23 = __floats2half2_rn(v.z, v.w);
    uint2 u;
    u.x = *(uint32_t*)&p01; u.y = *(uint32_t*)&p23;
    *(uint2*)(g_wt + (size_t)mat * D * D + (size_t)n * D + cg) = u;
}

// ---------------------------------------------------------------------------
// mma.sync fp16 2-term split dual-GEMM, GT=64, 2 CTAs/SM.
// Block: 64 rows x 128 cols, 256 threads. Warps 0-3: xl=A@Wl; 4-7: xr=A@Wr.
// Warp tile 32x64 = 2 m-frags x 8 n-frags (m16n8k16), K=128 in 8 steps.
// smem (fp16 elems): A_hi[64][136], A_lo[64][136], B[2][128][136] = 102 KB
// ---------------------------------------------------------------------------
#define AHI_OFF 0
#define ALO_OFF (GT * AST)                 // 8704
#define B_OFF   (2 * GT * AST)             // 17408
#define BIMG    (D * AST)                  // 17408
#define GSMEM_ELEMS (B_OFF + 2 * BIMG)     // 52224 fp16
#define GSMEM_BYTES (GSMEM_ELEMS * 2)      // 104448 B

__global__ __launch_bounds__(256, 2) void gemm_tc_kernel(
    const float* __restrict__ x_ext, int layer, int M, int tile0)
{
    extern __shared__ __half sm[];
    uint32_t sb = smem_u32(sm);
    const float* __restrict__ A = (layer == 0) ? x_ext : g_h;
    __half* __restrict__ xl_out = g_xl_h[layer];
    float*  __restrict__ xr_out = g_xr[layer];

    int tid = threadIdx.x;
    int wid = tid >> 5, l = tid & 31;
    int row0 = (tile0 + blockIdx.x) * GT;

    // ---- load A tile 64x128 fp32 -> fp16 hi/lo smem ----
    {
        int r = tid >> 2;                    // 0..63
        int cb = (tid & 3) * 32;
        int gr = row0 + r;
#pragma unroll
        for (int i = 0; i < 8; i++) {
            float4 v = make_float4(0.f, 0.f, 0.f, 0.f);
            if (gr < M) v = *(const float4*)(A + (size_t)gr * D + cb + i * 4);
            uint2 uhi, ulo;
            split_pack_h(v, uhi, ulo);
            *(uint2*)(sm + AHI_OFF + r * AST + cb + i * 4) = uhi;
            *(uint2*)(sm + ALO_OFF + r * AST + cb + i * 4) = ulo;
        }
    }
    // ---- load 2 weight images (layer-selected: Wl, Wr) into padded smem ----
    {
#pragma unroll
        for (int it = 0; it < 16; it++) {
            int idx = tid + it * 256;            // 0..4095
            int img = idx >> 11;                 // 0..1
            int rem = idx & 2047;
            int row = rem >> 4;
            int q   = rem & 15;
            const __half* src = g_wt + ((size_t)(layer * 2 + img) * D * D);
            uint4 v = ((const uint4*)(src + (size_t)row * D))[q];
            *(uint4*)(sm + B_OFF + img * BIMG + row * AST + q * 8) = v;
        }
    }
    __syncthreads();

    int mat = wid >> 2;                  // 0: Wl, 1: Wr
    int w = wid & 3;
    int wm = (w >> 1) * 32;              // 0 or 32 (rows)
    int wn = (w & 1) * 64;               // 0 or 64 (cols)

    uint32_t aHi[2], aLo[2];
#pragma unroll
    for (int mi = 0; mi < 2; mi++) {
        int ar = wm + mi * 16 + (l & 7) + ((l >> 3) & 1) * 8;
        int ac = ((l >> 4) & 1) * 8;
        aHi[mi] = sb + (uint32_t)(AHI_OFF + ar * AST + ac) * 2;
        aLo[mi] = sb + (uint32_t)(ALO_OFF + ar * AST + ac) * 2;
    }
    uint32_t bAddr[4];
#pragma unroll
    for (int jp = 0; jp < 4; jp++) {
        int br = wn + jp * 16 + (l & 7) + ((l >> 4) & 1) * 8;
        int bc = ((l >> 3) & 1) * 8;
        bAddr[jp] = sb + (uint32_t)(B_OFF + mat * BIMG + br * AST + bc) * 2;
    }

    float acc[2][8][4];
#pragma unroll
    for (int mi = 0; mi < 2; mi++)
#pragma unroll
        for (int nj = 0; nj < 8; nj++)
#pragma unroll
            for (int q = 0; q < 4; q++) acc[mi][nj][q] = 0.f;

#pragma unroll 1
    for (int ks = 0; ks < 8; ks++) {
        uint32_t kb = ks * 32;
        uint32_t ah[2][4], al[2][4], bh[8][2];
#pragma unroll
        for (int mi = 0; mi < 2; mi++) {
            LDSM4(ah[mi][0], ah[mi][1], ah[mi][2], ah[mi][3], aHi[mi] + kb);
            LDSM4(al[mi][0], al[mi][1], al[mi][2], al[mi][3], aLo[mi] + kb);
        }
#pragma unroll
        for (int jp = 0; jp < 4; jp++) {
            uint32_t r0, r1, r2, r3;
            LDSM4(r0, r1, r2, r3, bAddr[jp] + kb);
            bh[2 * jp][0] = r0; bh[2 * jp][1] = r1;
            bh[2 * jp + 1][0] = r2; bh[2 * jp + 1][1] = r3;
        }
#pragma unroll
        for (int mi = 0; mi < 2; mi++)
#pragma unroll
            for (int nj = 0; nj < 8; nj++) {
                MMA16816(acc[mi][nj], ah[mi], bh[nj]);
                MMA16816(acc[mi][nj], al[mi], bh[nj]);
            }
    }

    // ---- epilogue ----
    int g = l >> 2, t4 = l & 3;
#pragma unroll
    for (int mi = 0; mi < 2; mi++) {
        int r0 = row0 + wm + mi * 16 + g;
        int r1 = r0 + 8;
#pragma unroll
        for (int nj = 0; nj < 8; nj++) {
            int col = wn + nj * 8 + t4 * 2;
            if (mat == 0) {
                if (r0 < M) {
                    __half2 p = __floats2half2_rn(acc[mi][nj][0], acc[mi][nj][1]);
                    *(__half2*)(xl_out + (size_t)r0 * D + col) = p;
                }
                if (r1 < M) {
                    __half2 p = __floats2half2_rn(acc[mi][nj][2], acc[mi][nj][3]);
                    *(__half2*)(xl_out + (size_t)r1 * D + col) = p;
                }
            } else {
                if (r0 < M)
                    *(float2*)(xr_out + (size_t)r0 * D + col) =
                        make_float2(acc[mi][nj][0], acc[mi][nj][1]);
                if (r1 < M)
                    *(float2*)(xr_out + (size_t)r1 * D + col) =
                        make_float2(acc[mi][nj][2], acc[mi][nj][3]);
            }
        }
    }
}

// ---------------------------------------------------------------------------
// Fused aggregate + epilogue (R12-proven exact): one warp per dst node,
// uint2 (8B/lane) fp16 gathers, x4 unroll.
// ---------------------------------------------------------------------------
__device__ __forceinline__ void acc_half4(float4& acc, const __half* base, int c) {
    uint2 u = *(const uint2*)(base + c);
    float2 fa = __half22float2(*(__half2*)&u.x);
    float2 fb = __half22float2(*(__half2*)&u.y);
    acc.x += fa.x; acc.y += fa.y; acc.z += fb.x; acc.w += fb.y;
}

__global__ __launch_bounds__(256) void agg_finish_kernel(
    const float* __restrict__ b, float* __restrict__ out_ext,
    int layer, int n0, int n1)
{
    long long t = (long long)blockIdx.x * blockDim.x + threadIdx.x;
    int n = n0 + (int)(t >> 5);
    if (n >= n1) return;
    int c = ((int)t & 31) * 4;

    const __half* __restrict__ xl = g_xl_h[layer];
    const float*  __restrict__ xrb = g_xr[layer];

    float4 acc = make_float4(0.f, 0.f, 0.f, 0.f);
    int s = g_rowptr[n];
    int e = g_rowptr[n + 1];
    int i = s;
    for (; i + 3 < e; i += 4) {
        int m0 = g_srcs[i], m1 = g_srcs[i + 1], m2 = g_srcs[i + 2], m3 = g_srcs[i + 3];
        acc_half4(acc, xl + (size_t)m0 * D, c);
        acc_half4(acc, xl + (size_t)m1 * D, c);
        acc_half4(acc, xl + (size_t)m2 * D, c);
        acc_half4(acc, xl + (size_t)m3 * D, c);
    }
    for (; i < e; i++)
        acc_half4(acc, xl + (size_t)g_srcs[i] * D, c);

    float inv = g_inv[n];
    float4 xr = *(const float4*)(xrb + (size_t)n * D + c);
    float4 bv = *(const float4*)(b + c);
    float4 r;
    r.x = fmaxf(fmaf(acc.x, inv, xr.x + bv.x), 0.f);
    r.y = fmaxf(fmaf(acc.y, inv, xr.y + bv.y), 0.f);
    r.z = fmaxf(fmaf(acc.z, inv, xr.z + bv.z), 0.f);
    r.w = fmaxf(fmaf(acc.w, inv, xr.w + bv.w), 0.f);

    float* dst = (layer == 0) ? g_h : out_ext;
    *(float4*)(dst + (size_t)n * D + c) = r;
}

// ---------------------------------------------------------------------------
extern "C" void kernel_launch(void* const* d_in, const int* in_sizes, int n_in,
                              void* d_out, int out_size) {
    const float* x    = (const float*)d_in[0];
    const int*   ei   = (const int*)d_in[1];
    const float* W_l1 = (const float*)d_in[2];
    const float* W_r1 = (const float*)d_in[3];
    const float* b1   = (const float*)d_in[4];
    const float* W_l2 = (const float*)d_in[5];
    const float* W_r2 = (const float*)d_in[6];
    const float* b2   = (const float*)d_in[7];
    float* out        = (float*)d_out;

    int N = in_sizes[0] / D;   // 100000
    int E = in_sizes[1] / 2;   // 1600000

    // One-time resource setup on the first (correctness) call — before the
    // harness's pre-capture baseline. Capture call creates nothing.
    static cudaStream_t s1 = nullptr, s2 = nullptr;
    static cudaEvent_t evFork = nullptr, evCsr = nullptr, evW = nullptr,
                       evA0 = nullptr, evG0 = nullptr;
    if (s1 == nullptr) {
        cudaStreamCreateWithFlags(&s1, cudaStreamNonBlocking);
        cudaStreamCreateWithFlags(&s2, cudaStreamNonBlocking);
        cudaEventCreateWithFlags(&evFork, cudaEventDisableTiming);
        cudaEventCreateWithFlags(&evCsr, cudaEventDisableTiming);
        cudaEventCreateWithFlags(&evW, cudaEventDisableTiming);
        cudaEventCreateWithFlags(&evA0, cudaEventDisableTiming);
        cudaEventCreateWithFlags(&evG0, cudaEventDisableTiming);
        cudaFuncSetAttribute(gemm_tc_kernel,
                             cudaFuncAttributeMaxDynamicSharedMemorySize, GSMEM_BYTES);
    }

    int tb = 256;
    int grid_N    = (N + tb - 1) / tb;
    int grid_E    = (E + tb - 1) / tb;
    int tiles     = (N + GT - 1) / GT;               // 1563
    int tiles0    = tiles / 2;                       // 781
    int NH        = tiles0 * GT;                     // 49984
    int nblocks_scan = (N + SCH - 1) / SCH;

    auto agrid = [tb](int cnt) { return (int)(((long long)cnt * 32 + tb - 1) / tb); };

    cudaEventRecord(evFork, 0);

    // s1: CSR build (depends only on edge_index)
    cudaStreamWaitEvent(s1, evFork, 0);
    zero_cnt_kernel<<<grid_N, tb, 0, s1>>>(N);
    hist_kernel<<<grid_E, tb, 0, s1>>>(ei, E);
    scan1_kernel<<<nblocks_scan, SCH, 0, s1>>>(N);
    scan2_kernel<<<1, 256, 0, s1>>>(nblocks_scan);
    scan3_kernel<<<grid_N, tb, 0, s1>>>(N);
    fill_kernel<<<grid_E, tb, 0, s1>>>(ei, E);
    cudaEventRecord(evCsr, s1);

    // s2: weight transpose to fp16
    cudaStreamWaitEvent(s2, evFork, 0);
    wtrans_kernel<<<64, 256, 0, s2>>>(W_l1, W_r1, W_l2, W_r2);
    cudaEventRecord(evW, s2);

    // Layer 1 GEMM (full), CSR hidden behind it
    cudaStreamWaitEvent(0, evW, 0);
    gemm_tc_kernel<<<tiles, 256, GSMEM_BYTES>>>(x, 0, N, 0);

    // R12 structure: agg1 on C0, then gemm2(C0) on s2 || agg1(C1) on main.
    // gemm2 writes xl[1]/xr[1]; agg1 reads xl[0]/xr[0] — disjoint buffers.
    cudaStreamWaitEvent(0, evCsr, 0);
    agg_finish_kernel<<<agrid(NH), tb>>>(b1, out, 0, 0, NH);
    cudaEventRecord(evA0, 0);

    cudaStreamWaitEvent(s2, evA0, 0);
    gemm_tc_kernel<<<tiles0, 256, GSMEM_BYTES, s2>>>(x, 1, N, 0);
    cudaEventRecord(evG0, s2);

    agg_finish_kernel<<<agrid(N - NH), tb>>>(b1, out, 0, NH, N);
    gemm_tc_kernel<<<tiles - tiles0, 256, GSMEM_BYTES>>>(x, 1, N, tiles0);

    // Layer 2 aggregation needs all gemm2 halves
    cudaStreamWaitEvent(0, evG0, 0);
    agg_finish_kernel<<<agrid(N), tb>>>(b2, out, 1, 0, N);
}

// round 17
// speedup vs baseline: 1.2457x; 1.1069x over previous
#include <cuda_runtime.h>
#include <cuda_fp16.h>
#include <cstdint>

#define D 128
#define NMAX 100000
#define EMAX 1600000
#define SCH 512
#define GT 128                // gemm M tile
#define AST 136               // padded smem row stride (fp16 elems)

// Scratch (device globals — no runtime allocation allowed)
// xl / xr double-buffered per layer (race-free gemm2 || agg1 overlap).
__device__ __half g_xl_h[2][(size_t)NMAX * D]; // A @ W_l (fp16, gather-only)
__device__ float  g_xr[2][(size_t)NMAX * D];   // A @ W_r
__device__ float  g_h [(size_t)NMAX * D];      // layer-1 output
__device__ __half g_wt[4 * D * D];             // W^T fp16: Wl1,Wr1,Wl2,Wr2 ([n][k] row-major)
__device__ float  g_inv[NMAX];
__device__ int    g_cnt[NMAX];
__device__ int    g_fill[NMAX];
__device__ int    g_rowptr[NMAX + 1];
__device__ int    g_srcs[EMAX];
__device__ int    g_bsum[256];

// ---------------------------------------------------------------------------
__device__ __forceinline__ uint32_t smem_u32(const void* p) {
    uint32_t a;
    asm("{ .reg .u64 t; cvta.to.shared.u64 t, %1; cvt.u32.u64 %0, t; }" : "=r"(a) : "l"(p));
    return a;
}
// fp32x4 -> fp16x4 pack
__device__ __forceinline__ void pack_h(const float4 v, uint2& u) {
    __half2 h01 = __floats2half2_rn(v.x, v.y);
    __half2 h23 = __floats2half2_rn(v.z, v.w);
    u.x = *(uint32_t*)&h01; u.y = *(uint32_t*)&h23;
}
#define LDSM4(r0, r1, r2, r3, a) \
    asm volatile("ldmatrix.sync.aligned.m8n8.x4.shared.b16 {%0,%1,%2,%3}, [%4];" \
                 : "=r"(r0), "=r"(r1), "=r"(r2), "=r"(r3) : "r"(a))
#define MMA16816(c, a, b) \
    asm volatile("mma.sync.aligned.m16n8k16.row.col.f32.f16.f16.f32 " \
                 "{%0,%1,%2,%3}, {%4,%5,%6,%7}, {%8,%9}, {%0,%1,%2,%3};" \
                 : "+f"((c)[0]), "+f"((c)[1]), "+f"((c)[2]), "+f"((c)[3]) \
                 : "r"((a)[0]), "r"((a)[1]), "r"((a)[2]), "r"((a)[3]), \
                   "r"((b)[0]), "r"((b)[1]))

// ---------------------------------------------------------------------------
// CSR build
// ---------------------------------------------------------------------------
__global__ void zero_cnt_kernel(int N) {
    int i = blockIdx.x * blockDim.x + threadIdx.x;
    if (i < N) g_cnt[i] = 0;
}
__global__ void hist_kernel(const int* __restrict__ ei, int E) {
    int e = blockIdx.x * blockDim.x + threadIdx.x;
    if (e < E) atomicAdd(&g_cnt[ei[E + e]], 1);
}
__global__ __launch_bounds__(SCH) void scan1_kernel(int N) {
    __shared__ int sh[SCH];
    int t = threadIdx.x;
    int gi = blockIdx.x * SCH + t;
    sh[t] = (gi < N) ? g_cnt[gi] : 0;
    __syncthreads();
#pragma unroll
    for (int off = 1; off < SCH; off <<= 1) {
        int y = (t >= off) ? sh[t - off] : 0;
        __syncthreads();
        sh[t] += y;
        __syncthreads();
    }
    if (gi < N) g_rowptr[gi + 1] = sh[t];
    if (t == SCH - 1) g_bsum[blockIdx.x] = sh[t];
}
__global__ __launch_bounds__(256) void scan2_kernel(int nblocks) {
    __shared__ int sh[256];
    int t = threadIdx.x;
    sh[t] = (t < nblocks) ? g_bsum[t] : 0;
    __syncthreads();
#pragma unroll
    for (int off = 1; off < 256; off <<= 1) {
        int y = (t >= off) ? sh[t - off] : 0;
        __syncthreads();
        sh[t] += y;
        __syncthreads();
    }
    if (t < nblocks) g_bsum[t] = (t > 0) ? sh[t - 1] : 0;
}
__global__ void scan3_kernel(int N) {
    int i = blockIdx.x * blockDim.x + threadIdx.x;
    if (i >= N) return;
    int incl = g_rowptr[i + 1] + g_bsum[i / SCH];
    g_rowptr[i + 1] = incl;
    g_inv[i] = 1.0f / fmaxf((float)g_cnt[i], 1.0f);
    g_fill[i] = incl - g_cnt[i];   // cursor starts at rowptr[i]
    if (i == 0) g_rowptr[0] = 0;
}
__global__ void fill_kernel(const int* __restrict__ ei, int E) {
    int e = blockIdx.x * blockDim.x + threadIdx.x;
    if (e >= E) return;
    int d = ei[E + e];
    int pos = atomicAdd(&g_fill[d], 1);
    g_srcs[pos] = ei[e];
}

// ---------------------------------------------------------------------------
// wtrans: W[k][n] fp32 -> W^T[n][k] fp16 (4 matrices, row-major)
// ---------------------------------------------------------------------------
__global__ __launch_bounds__(256) void wtrans_kernel(
    const float* __restrict__ Wl1, const float* __restrict__ Wr1,
    const float* __restrict__ Wl2, const float* __restrict__ Wr2)
{
    int t = blockIdx.x * blockDim.x + threadIdx.x;   // 0 .. 16383
    int mat = t >> 12;
    int rem = t & 4095;
    int n = rem >> 5;
    int cg = (rem & 31) * 4;
    const float* W = (mat == 0) ? Wl1 : (mat == 1) ? Wr1 : (mat == 2) ? Wl2 : Wr2;
    float4 v;
    v.x = W[(cg + 0) * D + n];
    v.y = W[(cg + 1) * D + n];
    v.z = W[(cg + 2) * D + n];
    v.w = W[(cg + 3) * D + n];
    uint2 u;
    pack_h(v, u);
    *(uint2*)(g_wt + (size_t)mat * D * D + (size_t)n * D + cg) = u;
}

// ---------------------------------------------------------------------------
// mma.sync plain-fp16 dual-GEMM, GT=128 (single A term — no lo residual).
// Block: 128 rows x 128 cols, 256 threads. Warps 0-3: xl=A@Wl; 4-7: xr=A@Wr.
// Warp tile 64x64 = 4 m-frags x 8 n-frags (m16n8k16), K=128 in 8 steps.
// smem (fp16 elems): A[128][136], B[2][128][136] = 104448 B
// ---------------------------------------------------------------------------
#define A_OFF   0
#define B_OFF   (GT * AST)                 // 17408
#define BIMG    (D * AST)                  // 17408
#define GSMEM_ELEMS (B_OFF + 2 * BIMG)     // 52224 fp16
#define GSMEM_BYTES (GSMEM_ELEMS * 2)      // 104448 B

__global__ __launch_bounds__(256, 1) void gemm_tc_kernel(
    const float* __restrict__ x_ext, int layer, int M, int tile0)
{
    extern __shared__ __half sm[];
    uint32_t sb = smem_u32(sm);
    const float* __restrict__ A = (layer == 0) ? x_ext : g_h;
    __half* __restrict__ xl_out = g_xl_h[layer];
    float*  __restrict__ xr_out = g_xr[layer];

    int tid = threadIdx.x;
    int wid = tid >> 5, l = tid & 31;
    int row0 = (tile0 + blockIdx.x) * GT;

    // ---- load A tile 128x128 fp32 -> fp16 smem ----
    {
        int r = tid >> 1;                    // 0..127
        int cb = (tid & 1) * 64;
        int gr = row0 + r;
#pragma unroll
        for (int i = 0; i < 16; i++) {
            float4 v = make_float4(0.f, 0.f, 0.f, 0.f);
            if (gr < M) v = *(const float4*)(A + (size_t)gr * D + cb + i * 4);
            uint2 u;
            pack_h(v, u);
            *(uint2*)(sm + A_OFF + r * AST + cb + i * 4) = u;
        }
    }
    // ---- load 2 weight images (layer-selected: Wl, Wr) into padded smem ----
    {
#pragma unroll
        for (int it = 0; it < 16; it++) {
            int idx = tid + it * 256;            // 0..4095
            int img = idx >> 11;                 // 0..1
            int rem = idx & 2047;
            int row = rem >> 4;
            int q   = rem & 15;
            const __half* src = g_wt + ((size_t)(layer * 2 + img) * D * D);
            uint4 v = ((const uint4*)(src + (size_t)row * D))[q];
            *(uint4*)(sm + B_OFF + img * BIMG + row * AST + q * 8) = v;
        }
    }
    __syncthreads();

    int mat = wid >> 2;                  // 0: Wl, 1: Wr
    int w = wid & 3;
    int wm = (w >> 1) * 64;
    int wn = (w & 1) * 64;

    uint32_t aAddr[4];
#pragma unroll
    for (int mi = 0; mi < 4; mi++) {
        int ar = wm + mi * 16 + (l & 7) + ((l >> 3) & 1) * 8;
        int ac = ((l >> 4) & 1) * 8;
        aAddr[mi] = sb + (uint32_t)(A_OFF + ar * AST + ac) * 2;
    }
    uint32_t bAddr[4];
#pragma unroll
    for (int jp = 0; jp < 4; jp++) {
        int br = wn + jp * 16 + (l & 7) + ((l >> 4) & 1) * 8;
        int bc = ((l >> 3) & 1) * 8;
        bAddr[jp] = sb + (uint32_t)(B_OFF + mat * BIMG + br * AST + bc) * 2;
    }

    float acc[4][8][4];
#pragma unroll
    for (int mi = 0; mi < 4; mi++)
#pragma unroll
        for (int nj = 0; nj < 8; nj++)
#pragma unroll
            for (int q = 0; q < 4; q++) acc[mi][nj][q] = 0.f;

#pragma unroll 1
    for (int ks = 0; ks < 8; ks++) {
        uint32_t kb = ks * 32;
        uint32_t ah[4][4], bh[8][2];
#pragma unroll
        for (int mi = 0; mi < 4; mi++)
            LDSM4(ah[mi][0], ah[mi][1], ah[mi][2], ah[mi][3], aAddr[mi] + kb);
#pragma unroll
        for (int jp = 0; jp < 4; jp++) {
            uint32_t r0, r1, r2, r3;
            LDSM4(r0, r1, r2, r3, bAddr[jp] + kb);
            bh[2 * jp][0] = r0; bh[2 * jp][1] = r1;
            bh[2 * jp + 1][0] = r2; bh[2 * jp + 1][1] = r3;
        }
#pragma unroll
        for (int mi = 0; mi < 4; mi++)
#pragma unroll
            for (int nj = 0; nj < 8; nj++)
                MMA16816(acc[mi][nj], ah[mi], bh[nj]);
    }

    // ---- epilogue ----
    int g = l >> 2, t4 = l & 3;
#pragma unroll
    for (int mi = 0; mi < 4; mi++) {
        int r0 = row0 + wm + mi * 16 + g;
        int r1 = r0 + 8;
#pragma unroll
        for (int nj = 0; nj < 8; nj++) {
            int col = wn + nj * 8 + t4 * 2;
            if (mat == 0) {
                if (r0 < M) {
                    __half2 p = __floats2half2_rn(acc[mi][nj][0], acc[mi][nj][1]);
                    *(__half2*)(xl_out + (size_t)r0 * D + col) = p;
                }
                if (r1 < M) {
                    __half2 p = __floats2half2_rn(acc[mi][nj][2], acc[mi][nj][3]);
                    *(__half2*)(xl_out + (size_t)r1 * D + col) = p;
                }
            } else {
                if (r0 < M)
                    *(float2*)(xr_out + (size_t)r0 * D + col) =
                        make_float2(acc[mi][nj][0], acc[mi][nj][1]);
                if (r1 < M)
                    *(float2*)(xr_out + (size_t)r1 * D + col) =
                        make_float2(acc[mi][nj][2], acc[mi][nj][3]);
            }
        }
    }
}

// ---------------------------------------------------------------------------
// Fused aggregate + epilogue (R12-proven exact): one warp per dst node,
// uint2 (8B/lane) fp16 gathers, x4 unroll.
// ---------------------------------------------------------------------------
__device__ __forceinline__ void acc_half4(float4& acc, const __half* base, int c) {
    uint2 u = *(const uint2*)(base + c);
    float2 fa = __half22float2(*(__half2*)&u.x);
    float2 fb = __half22float2(*(__half2*)&u.y);
    acc.x += fa.x; acc.y += fa.y; acc.z += fb.x; acc.w += fb.y;
}

__global__ __launch_bounds__(256) void agg_finish_kernel(
    const float* __restrict__ b, float* __restrict__ out_ext,
    int layer, int n0, int n1)
{
    long long t = (long long)blockIdx.x * blockDim.x + threadIdx.x;
    int n = n0 + (int)(t >> 5);
    if (n >= n1) return;
    int c = ((int)t & 31) * 4;

    const __half* __restrict__ xl = g_xl_h[layer];
    const float*  __restrict__ xrb = g_xr[layer];

    float4 acc = make_float4(0.f, 0.f, 0.f, 0.f);
    int s = g_rowptr[n];
    int e = g_rowptr[n + 1];
    int i = s;
    for (; i + 3 < e; i += 4) {
        int m0 = g_srcs[i], m1 = g_srcs[i + 1], m2 = g_srcs[i + 2], m3 = g_srcs[i + 3];
        acc_half4(acc, xl + (size_t)m0 * D, c);
        acc_half4(acc, xl + (size_t)m1 * D, c);
        acc_half4(acc, xl + (size_t)m2 * D, c);
        acc_half4(acc, xl + (size_t)m3 * D, c);
    }
    for (; i < e; i++)
        acc_half4(acc, xl + (size_t)g_srcs[i] * D, c);

    float inv = g_inv[n];
    float4 xr = *(const float4*)(xrb + (size_t)n * D + c);
    float4 bv = *(const float4*)(b + c);
    float4 r;
    r.x = fmaxf(fmaf(acc.x, inv, xr.x + bv.x), 0.f);
    r.y = fmaxf(fmaf(acc.y, inv, xr.y + bv.y), 0.f);
    r.z = fmaxf(fmaf(acc.z, inv, xr.z + bv.z), 0.f);
    r.w = fmaxf(fmaf(acc.w, inv, xr.w + bv.w), 0.f);

    float* dst = (layer == 0) ? g_h : out_ext;
    *(float4*)(dst + (size_t)n * D + c) = r;
}

// ---------------------------------------------------------------------------
extern "C" void kernel_launch(void* const* d_in, const int* in_sizes, int n_in,
                              void* d_out, int out_size) {
    const float* x    = (const float*)d_in[0];
    const int*   ei   = (const int*)d_in[1];
    const float* W_l1 = (const float*)d_in[2];
    const float* W_r1 = (const float*)d_in[3];
    const float* b1   = (const float*)d_in[4];
    const float* W_l2 = (const float*)d_in[5];
    const float* W_r2 = (const float*)d_in[6];
    const float* b2   = (const float*)d_in[7];
    float* out        = (float*)d_out;

    int N = in_sizes[0] / D;   // 100000
    int E = in_sizes[1] / 2;   // 1600000

    // One-time resource setup on the first (correctness) call — before the
    // harness's pre-capture baseline. Capture call creates nothing.
    static cudaStream_t s1 = nullptr, s2 = nullptr;
    static cudaEvent_t evFork = nullptr, evCsr = nullptr, evW = nullptr,
                       evA0 = nullptr, evG0 = nullptr;
    if (s1 == nullptr) {
        cudaStreamCreateWithFlags(&s1, cudaStreamNonBlocking);
        cudaStreamCreateWithFlags(&s2, cudaStreamNonBlocking);
        cudaEventCreateWithFlags(&evFork, cudaEventDisableTiming);
        cudaEventCreateWithFlags(&evCsr, cudaEventDisableTiming);
        cudaEventCreateWithFlags(&evW, cudaEventDisableTiming);
        cudaEventCreateWithFlags(&evA0, cudaEventDisableTiming);
        cudaEventCreateWithFlags(&evG0, cudaEventDisableTiming);
        cudaFuncSetAttribute(gemm_tc_kernel,
                             cudaFuncAttributeMaxDynamicSharedMemorySize, GSMEM_BYTES);
    }

    int tb = 256;
    int grid_N    = (N + tb - 1) / tb;
    int grid_E    = (E + tb - 1) / tb;
    int tiles     = (N + GT - 1) / GT;               // 782
    int tiles0    = tiles / 2;                       // 391
    int NH        = tiles0 * GT;                     // 50048
    int nblocks_scan = (N + SCH - 1) / SCH;

    auto agrid = [tb](int cnt) { return (int)(((long long)cnt * 32 + tb - 1) / tb); };

    cudaEventRecord(evFork, 0);

    // s1: CSR build (depends only on edge_index)
    cudaStreamWaitEvent(s1, evFork, 0);
    zero_cnt_kernel<<<grid_N, tb, 0, s1>>>(N);
    hist_kernel<<<grid_E, tb, 0, s1>>>(ei, E);
    scan1_kernel<<<nblocks_scan, SCH, 0, s1>>>(N);
    scan2_kernel<<<1, 256, 0, s1>>>(nblocks_scan);
    scan3_kernel<<<grid_N, tb, 0, s1>>>(N);
    fill_kernel<<<grid_E, tb, 0, s1>>>(ei, E);
    cudaEventRecord(evCsr, s1);

    // s2: weight transpose to fp16
    cudaStreamWaitEvent(s2, evFork, 0);
    wtrans_kernel<<<64, 256, 0, s2>>>(W_l1, W_r1, W_l2, W_r2);
    cudaEventRecord(evW, s2);

    // Layer 1 GEMM (full), CSR hidden behind it
    cudaStreamWaitEvent(0, evW, 0);
    gemm_tc_kernel<<<tiles, 256, GSMEM_BYTES>>>(x, 0, N, 0);

    // R12 structure: agg1 on C0, then gemm2(C0) on s2 || agg1(C1) on main.
    // gemm2 writes xl[1]/xr[1]; agg1 reads xl[0]/xr[0] — disjoint buffers.
    cudaStreamWaitEvent(0, evCsr, 0);
    agg_finish_kernel<<<agrid(NH), tb>>>(b1, out, 0, 0, NH);
    cudaEventRecord(evA0, 0);

    cudaStreamWaitEvent(s2, evA0, 0);
    gemm_tc_kernel<<<tiles0, 256, GSMEM_BYTES, s2>>>(x, 1, N, 0);
    cudaEventRecord(evG0, s2);

    agg_finish_kernel<<<agrid(N - NH), tb>>>(b1, out, 0, NH, N);
    gemm_tc_kernel<<<tiles - tiles0, 256, GSMEM_BYTES>>>(x, 1, N, tiles0);

    // Layer 2 aggregation needs both gemm2 halves
    cudaStreamWaitEvent(0, evG0, 0);
    agg_finish_kernel<<<agrid(N), tb>>>(b2, out, 1, 0, N);
}